// round 17
// baseline (speedup 1.0000x reference)
#include <cuda_runtime.h>

// 4-D average pool, kernel=stride=2, padding=0.
// Input : [2, 16, 32, 32, 32, 32] fp32  (33,554,432 elems, 128 MiB)
// Output: [2, 16, 16, 16, 16, 16] fp32  ( 2,097,152 elems,   8 MiB)
//
// History: R9 regs=32 serialized loads (DRAM 70.9%). R13: bounds(256,3),
// array-load-then-reduce -> regs=70, MLP=16, 24 warps/SM, DRAM 76.5%,
// kernel 22.88us (best). R14 persistent grid REGRESSED (loop serializes
// load batches across iterations) -> reverted to 2048 independent CTAs.
// R15/16: bounds(256,4) -> 64-reg ceiling. ptxas keeps ~12-14 loads live
// (slightly lower MLP) but occupancy rises to 32 warps/SM: in-flight
// bytes/SM ~53KB > R13's 42KB, and more warps issue/overlap stores.

#define OUT_D  16           // output extent of each pooled dim
#define QUADS_PER_ROW 4     // OUT_D / 4 output-quads along last dim

template <bool GUARD>
__global__ __launch_bounds__(256, 4)
void avgpool4d_k2s2_kernel(const float4* __restrict__ in4,
                           float4* __restrict__ out4,
                           unsigned n_quads)
{
    unsigned q = blockIdx.x * blockDim.x + threadIdx.x;
    if (GUARD && q >= n_quads) return;

    // Decompose quad index q over output [BC, 16, 16, 16, 4 quads]
    unsigned q4 = q & (QUADS_PER_ROW - 1);       // quad index along d4
    unsigned r  = q >> 2;
    unsigned d3 = r & (OUT_D - 1);  r >>= 4;
    unsigned d2 = r & (OUT_D - 1);  r >>= 4;
    unsigned d1 = r & (OUT_D - 1);  r >>= 4;
    unsigned bc = r;                             // 0..31 (B*C)

    // Base index in float4 units:
    // float4 strides: bc:262144, i1:8192, i2:256, i3:8, q4 step:2
    unsigned base = bc * 262144u + d1 * 16384u + d2 * 512u + d3 * 16u + q4 * 2u;

    const unsigned S1 = 8192u;   // +1 in i1 (float4 units)
    const unsigned S2 = 256u;    // +1 in i2
    const unsigned S3 = 8u;      // +1 in i3

    // Offsets of the 8 corners of the 2x2x2 (d1,d2,d3) window.
    const unsigned off[8] = {
        0u,        S3,        S2,        S2 + S3,
        S1,        S1 + S3,   S1 + S2,   S1 + S2 + S3
    };

    // Phase 1: issue the 16 independent 128-bit streaming loads.
    // (Under the 64-reg ceiling ptxas keeps ~12-14 in flight.)
    float4 v[16];
#pragma unroll
    for (int c = 0; c < 8; ++c) {
        v[2*c]     = __ldcs(in4 + base + off[c]);
        v[2*c + 1] = __ldcs(in4 + base + off[c] + 1);
    }

    // Phase 2: reduce. Output j (0..3) sums i4 = {2j, 2j+1} over 8 corners.
    float o0 = 0.f, o1 = 0.f, o2 = 0.f, o3 = 0.f;
#pragma unroll
    for (int c = 0; c < 8; ++c) {
        o0 += v[2*c].x + v[2*c].y;
        o1 += v[2*c].z + v[2*c].w;
        o2 += v[2*c + 1].x + v[2*c + 1].y;
        o3 += v[2*c + 1].z + v[2*c + 1].w;
    }

    const float inv16 = 0.0625f;   // 1/2^4
    __stcs(out4 + q, make_float4(o0 * inv16, o1 * inv16, o2 * inv16, o3 * inv16));
}

extern "C" void kernel_launch(void* const* d_in, const int* in_sizes, int n_in,
                              void* d_out, int out_size)
{
    const float4* in4 = (const float4*)d_in[0];
    float4* out4 = (float4*)d_out;

    unsigned n_quads = (unsigned)(out_size / 4);         // 524,288
    const unsigned threads = 256;

    if (n_quads % threads == 0) {
        // Exact grid (2048 blocks): fine quanta, no bounds guard.
        avgpool4d_k2s2_kernel<false><<<n_quads / threads, threads>>>(in4, out4, n_quads);
    } else {
        unsigned blocks = (n_quads + threads - 1) / threads;
        avgpool4d_k2s2_kernel<true><<<blocks, threads>>>(in4, out4, n_quads);
    }
}